// round 10
// baseline (speedup 1.0000x reference)
#include <cuda_runtime.h>
#include <cuda_bf16.h>
#include <math.h>
#include <stdint.h>

// ---------------- problem constants ----------------
#define BT      3136
#define NJ      43
#define NJ6     13
#define DLAT    512
#define OUTC    168

// ---------------- tiling ----------------
#define TM       64       // tokens per CTA
#define NCHUNK   128      // N per chunk (4 chunks)
#define KCH      64       // K per chunk (8 chunks)
#define NTHREADS 256      // 8 warps: 2 (m) x 4 (n), warp tile m32 n32

// ---------------- smem layout (bytes), fits 2 CTAs/SM ----------------
// A: 2 stages x (hi 8K + lo 8K)  = 32768
// B: 2 stages x (hi 16K + lo 16K)= 65536
// b1s: 512 fp32                  = 2048
// w2t: [6][516] fp32             = 12384
// red: [4][64][8] fp32 aliased onto A region (dead after last MMA)
#define A_HI(b)  ((b)*16384)
#define A_LO(b)  ((b)*16384 + 8192)
#define OFF_B    32768
#define B_HI(b)  (OFF_B + (b)*32768)
#define B_LO(b)  (OFF_B + (b)*32768 + 16384)
#define OFF_B1   98304
#define OFF_W2T  100352
#define W2STR    516
#define OFF_RED  0
#define SMEM_BYTES 112736

#define ASWZ(x) ((x) ^ (((x) >> 3) & 0x70))   // 128B rows
#define BSWZ(x) ((x) ^ (((x) >> 4) & 0x70))   // 256B rows

// ---------------- device scratch: preconverted bf16 hi/lo ----------------
__device__ __nv_bfloat16 g_w1hi[(size_t)NJ * DLAT * DLAT];
__device__ __nv_bfloat16 g_w1lo[(size_t)NJ * DLAT * DLAT];
__device__ __nv_bfloat16 g_xhi[(size_t)BT * NJ * DLAT];
__device__ __nv_bfloat16 g_xlo[(size_t)BT * NJ * DLAT];

__device__ __forceinline__ uint32_t smem_u32(const void* p) {
    uint32_t a;
    asm("{ .reg .u64 t; cvta.to.shared.u64 t, %1; cvt.u32.u64 %0, t; }" : "=r"(a) : "l"(p));
    return a;
}

__device__ __forceinline__ float gelu_erf(float v) {
    return 0.5f * v * (1.0f + erff(v * 0.70710678118654752f));
}

// ---------------- bf16 split helpers ----------------
__device__ __forceinline__ uint32_t pk(__nv_bfloat16 a, __nv_bfloat16 b) {
    return (uint32_t)__bfloat16_as_ushort(a) | ((uint32_t)__bfloat16_as_ushort(b) << 16);
}
__device__ __forceinline__ void split4(float4 v, uint2* h, uint2* l) {
    __nv_bfloat16 bx = __float2bfloat16(v.x), by = __float2bfloat16(v.y);
    __nv_bfloat16 bz = __float2bfloat16(v.z), bw = __float2bfloat16(v.w);
    h->x = pk(bx, by); h->y = pk(bz, bw);
    __nv_bfloat16 lx = __float2bfloat16(v.x - __bfloat162float(bx));
    __nv_bfloat16 ly = __float2bfloat16(v.y - __bfloat162float(by));
    __nv_bfloat16 lz = __float2bfloat16(v.z - __bfloat162float(bz));
    __nv_bfloat16 lw = __float2bfloat16(v.w - __bfloat162float(bw));
    l->x = pk(lx, ly); l->y = pk(lz, lw);
}

// ---------------- cp.async ----------------
__device__ __forceinline__ void cpa16(uint32_t dst, const void* src, int ssz) {
    asm volatile("cp.async.cg.shared.global [%0], [%1], 16, %2;"
                 :: "r"(dst), "l"(src), "r"(ssz) : "memory");
}
#define CP_COMMIT() asm volatile("cp.async.commit_group;" ::: "memory")
#define CP_WAIT0()  asm volatile("cp.async.wait_group 0;" ::: "memory")

// ---------------- mma / ldmatrix ----------------
__device__ __forceinline__ void ldsm4(uint32_t* r, uint32_t addr) {
    asm volatile("ldmatrix.sync.aligned.m8n8.x4.shared.b16 {%0,%1,%2,%3}, [%4];"
                 : "=r"(r[0]), "=r"(r[1]), "=r"(r[2]), "=r"(r[3]) : "r"(addr));
}
__device__ __forceinline__ void ldsm4t(uint32_t* r, uint32_t addr) {
    asm volatile("ldmatrix.sync.aligned.m8n8.x4.trans.shared.b16 {%0,%1,%2,%3}, [%4];"
                 : "=r"(r[0]), "=r"(r[1]), "=r"(r[2]), "=r"(r[3]) : "r"(addr));
}
__device__ __forceinline__ void mma16816(float* c, const uint32_t* a, const uint32_t* b) {
    asm volatile("mma.sync.aligned.m16n8k16.row.col.f32.bf16.bf16.f32 "
                 "{%0,%1,%2,%3}, {%4,%5,%6,%7}, {%8,%9}, {%0,%1,%2,%3};"
                 : "+f"(c[0]), "+f"(c[1]), "+f"(c[2]), "+f"(c[3])
                 : "r"(a[0]), "r"(a[1]), "r"(a[2]), "r"(a[3]), "r"(b[0]), "r"(b[1]));
}

// ---------------- merged preconvert kernel (W1 then x) ----------------
#define W1F4 2818048u      // 43*512*512/4
#define XF4  17260544u     // 3136*43*512/4
__global__ __launch_bounds__(512, 2)
void convert_all_kernel(const float* __restrict__ W1, const float* __restrict__ x) {
    const uint32_t idx = blockIdx.x * 512u + threadIdx.x;   // exact grid: W1F4+XF4
    if (idx < W1F4) {
        const float4 v = ((const float4*)W1)[idx];
        uint2 h, l; split4(v, &h, &l);
        ((uint2*)g_w1hi)[idx] = h;
        ((uint2*)g_w1lo)[idx] = l;
    } else {
        const uint32_t i2 = idx - W1F4;
        const float4 v = ((const float4*)x)[i2];
        uint2 h, l; split4(v, &h, &l);
        ((uint2*)g_xhi)[i2] = h;
        ((uint2*)g_xlo)[i2] = l;
    }
}

// ---------------- prefetch (bf16 gmem -> swizzled smem) ----------------
__device__ __forceinline__ void prefetch_a(uint32_t smb, int buf, int j, int tok0,
                                           int kc, int tid) {
    #pragma unroll
    for (int r = 0; r < 2; ++r) {
        const int idx = tid + r * NTHREADS;     // 0..511
        const int m = idx >> 3, k8 = idx & 7;
        const int token = tok0 + m;
        const size_t g = ((size_t)token * NJ + j) * DLAT + kc * KCH + k8 * 8;
        const int ssz = (token < BT) ? 16 : 0;
        const uint32_t o = ASWZ((uint32_t)(m * 128 + k8 * 16));
        cpa16(smb + A_HI(buf) + o, g_xhi + g, ssz);
        cpa16(smb + A_LO(buf) + o, g_xlo + g, ssz);
    }
}
__device__ __forceinline__ void prefetch_b(uint32_t smb, int buf, int j, int kc,
                                           int nc, int tid) {
    const size_t base = (size_t)j * DLAT * DLAT + (size_t)(kc * KCH) * DLAT + nc * NCHUNK;
    #pragma unroll
    for (int r = 0; r < 4; ++r) {
        const int idx = tid + r * NTHREADS;     // 0..1023
        const int k = idx >> 4, n16 = idx & 15;
        const size_t g = base + (size_t)k * DLAT + n16 * 8;
        const uint32_t o = BSWZ((uint32_t)(k * 256 + n16 * 16));
        cpa16(smb + B_HI(buf) + o, g_w1hi + g, 16);
        cpa16(smb + B_LO(buf) + o, g_w1lo + g, 16);
    }
}

// ---------------- main kernel ----------------
__global__ __launch_bounds__(NTHREADS, 2)
void motion_decoder_mma(const float* __restrict__ b1,
                        const float* __restrict__ W2a,
                        const float* __restrict__ b2a,
                        const float* __restrict__ W2b,
                        const float* __restrict__ b2b,
                        float* __restrict__ out)
{
    extern __shared__ char sm[];
    const uint32_t smb = smem_u32(sm);
    const int tid = threadIdx.x;
    const int wid = tid >> 5, lane = tid & 31;
    const int wm = wid >> 2;               // 0..1 -> m offset wm*32
    const int wn = wid & 3;                // 0..3 -> n offset wn*32
    const int j = blockIdx.y;
    const int tok0 = blockIdx.x * TM;

    const int odim = (j < NJ6) ? 6 : 3;
    const float* W2 = (j < NJ6) ? (W2a + (size_t)j * DLAT * 6)
                                : (W2b + (size_t)(j - NJ6) * DLAT * 3);
    const float* b2 = (j < NJ6) ? (b2a + j * 6) : (b2b + (j - NJ6) * 3);
    const int colbase = (j < NJ6) ? j * 6 : (NJ6 * 6 + (j - NJ6) * 3);

    // pipeline prologue: stage 0 in flight
    prefetch_a(smb, 0, j, tok0, 0, tid);
    prefetch_b(smb, 0, j, 0, 0, tid);
    CP_COMMIT();

    // preload b1 and W2 (transposed to [o][n], zero-padded rows for odim==3)
    float* b1s = (float*)(sm + OFF_B1);
    for (int i = tid; i < DLAT; i += NTHREADS) b1s[i] = b1[j * DLAT + i];
    float* w2t = (float*)(sm + OFF_W2T);
    for (int i = tid; i < 6 * DLAT; i += NTHREADS) {
        const int o = i / DLAT, n = i - o * DLAT;
        w2t[o * W2STR + n] = (o < odim) ? W2[n * odim + o] : 0.f;
    }

    const int l15 = lane & 15;
    const int lhi = lane >> 4;

    // GEMM2 accumulators: [mt][rowhalf][o]
    float oacc[2][2][6];
    #pragma unroll
    for (int a = 0; a < 2; ++a)
        #pragma unroll
        for (int b = 0; b < 2; ++b)
            #pragma unroll
            for (int o = 0; o < 6; ++o) oacc[a][b][o] = 0.f;

    #pragma unroll 1
    for (int nc = 0; nc < 4; ++nc) {
        float c[2][4][4];
        #pragma unroll
        for (int mt = 0; mt < 2; ++mt)
            #pragma unroll
            for (int nt = 0; nt < 4; ++nt)
                #pragma unroll
                for (int q = 0; q < 4; ++q) c[mt][nt][q] = 0.f;

        #pragma unroll 1
        for (int kc = 0; kc < 8; ++kc) {
            const int s = nc * 8 + kc;
            CP_WAIT0();                    // stage s resident
            __syncthreads();               // visible; prior readers done

            if (s < 31) {                  // prefetch s+1 during MMA(s)
                const int s2 = s + 1;
                prefetch_a(smb, s2 & 1, j, tok0, s2 & 7, tid);
                prefetch_b(smb, s2 & 1, j, s2 & 7, s2 >> 3, tid);
                CP_COMMIT();
            }

            const int buf = s & 1;
            const uint32_t abh = smb + A_HI(buf), abl = smb + A_LO(buf);
            const uint32_t bbh = smb + B_HI(buf), bbl = smb + B_LO(buf);

            #pragma unroll
            for (int kt = 0; kt < 4; ++kt) {
                uint32_t ah[2][4], bh[2][4], bl[2][4], al[4];
                #pragma unroll
                for (int mt = 0; mt < 2; ++mt) {
                    const int row = wm * 32 + mt * 16 + l15;
                    ldsm4(ah[mt], abh + ASWZ((uint32_t)(row * 128 + kt * 32 + lhi * 16)));
                }
                #pragma unroll
                for (int nt2 = 0; nt2 < 2; ++nt2) {
                    const int krow = kt * 16 + l15;
                    ldsm4t(bh[nt2], bbh + BSWZ((uint32_t)(krow * 256 + wn * 64 + nt2 * 32 + lhi * 16)));
                }
                #pragma unroll
                for (int mt = 0; mt < 2; ++mt)
                    #pragma unroll
                    for (int nt = 0; nt < 4; ++nt)
                        mma16816(c[mt][nt], ah[mt], &bh[nt >> 1][(nt & 1) * 2]);
                #pragma unroll
                for (int nt2 = 0; nt2 < 2; ++nt2) {
                    const int krow = kt * 16 + l15;
                    ldsm4t(bl[nt2], bbl + BSWZ((uint32_t)(krow * 256 + wn * 64 + nt2 * 32 + lhi * 16)));
                }
                #pragma unroll
                for (int mt = 0; mt < 2; ++mt)
                    #pragma unroll
                    for (int nt = 0; nt < 4; ++nt)
                        mma16816(c[mt][nt], ah[mt], &bl[nt >> 1][(nt & 1) * 2]);
                #pragma unroll
                for (int mt = 0; mt < 2; ++mt) {
                    const int row = wm * 32 + mt * 16 + l15;
                    ldsm4(al, abl + ASWZ((uint32_t)(row * 128 + kt * 32 + lhi * 16)));
                    #pragma unroll
                    for (int nt = 0; nt < 4; ++nt)
                        mma16816(c[mt][nt], al, &bh[nt >> 1][(nt & 1) * 2]);
                }
            }
        }

        // ---- fused epilogue: bias + GELU + GEMM2 partial, registers only ----
        #pragma unroll
        for (int nt = 0; nt < 4; ++nt) {
            const int ncol = wn * 32 + nt * 8 + (lane & 3) * 2;
            const int ng = nc * NCHUNK + ncol;
            const float bv0 = b1s[ng], bv1 = b1s[ng + 1];
            #pragma unroll
            for (int mt = 0; mt < 2; ++mt) {
                const float h0 = gelu_erf(c[mt][nt][0] + bv0);
                const float h1 = gelu_erf(c[mt][nt][1] + bv1);
                const float h2 = gelu_erf(c[mt][nt][2] + bv0);
                const float h3 = gelu_erf(c[mt][nt][3] + bv1);
                if (odim == 6) {
                    #pragma unroll
                    for (int o = 0; o < 6; ++o) {
                        const float w0 = w2t[o * W2STR + ng];
                        const float w1 = w2t[o * W2STR + ng + 1];
                        oacc[mt][0][o] += h0 * w0 + h1 * w1;
                        oacc[mt][1][o] += h2 * w0 + h3 * w1;
                    }
                } else {
                    #pragma unroll
                    for (int o = 0; o < 3; ++o) {
                        const float w0 = w2t[o * W2STR + ng];
                        const float w1 = w2t[o * W2STR + ng + 1];
                        oacc[mt][0][o] += h0 * w0 + h1 * w1;
                        oacc[mt][1][o] += h2 * w0 + h3 * w1;
                    }
                }
            }
        }
    }

    // ---- reduction: quad butterfly, then cross-warp via smem (aliased on A) ----
    #pragma unroll
    for (int mt = 0; mt < 2; ++mt)
        #pragma unroll
        for (int i = 0; i < 2; ++i)
            #pragma unroll
            for (int o = 0; o < 6; ++o) {
                float v = oacc[mt][i][o];
                v += __shfl_xor_sync(0xffffffffu, v, 1);
                v += __shfl_xor_sync(0xffffffffu, v, 2);
                oacc[mt][i][o] = v;
            }

    float* red = (float*)(sm + OFF_RED);
    __syncthreads();                       // all MMA reads of A done (alias safety)
    if ((lane & 3) == 0) {
        const int g = lane >> 2;
        #pragma unroll
        for (int mt = 0; mt < 2; ++mt)
            #pragma unroll
            for (int i = 0; i < 2; ++i) {
                const int row = wm * 32 + mt * 16 + i * 8 + g;
                #pragma unroll
                for (int o = 0; o < 6; ++o)
                    red[(wn * TM + row) * 8 + o] = oacc[mt][i][o];
            }
    }
    __syncthreads();

    #pragma unroll
    for (int p = 0; p < 2; ++p) {
        const int idx = tid + p * NTHREADS;
        if (idx < TM * odim) {
            const int m = idx / odim;
            const int o = idx - m * odim;
            const int token = tok0 + m;
            if (token < BT) {
                const float sdm = red[m * 8 + o] + red[(TM + m) * 8 + o]
                                + red[(2 * TM + m) * 8 + o] + red[(3 * TM + m) * 8 + o];
                out[(size_t)token * OUTC + colbase + o] = sdm + b2[o];
            }
        }
    }
}

extern "C" void kernel_launch(void* const* d_in, const int* in_sizes, int n_in,
                              void* d_out, int out_size)
{
    const float* x   = (const float*)d_in[0];
    const float* W1  = (const float*)d_in[1];
    const float* b1  = (const float*)d_in[2];
    const float* W2a = (const float*)d_in[3];
    const float* b2a = (const float*)d_in[4];
    const float* W2b = (const float*)d_in[5];
    const float* b2b = (const float*)d_in[6];
    float* out = (float*)d_out;

    // 1) preconvert W1 + x to bf16 hi/lo, single launch (exact grid)
    convert_all_kernel<<<(W1F4 + XF4) / 512, 512>>>(W1, x);

    // 2) fused split-GEMM, 2 CTAs/SM
    cudaFuncSetAttribute(motion_decoder_mma,
                         cudaFuncAttributeMaxDynamicSharedMemorySize, SMEM_BYTES);
    dim3 grid((BT + TM - 1) / TM, NJ);          // 49 x 43
    motion_decoder_mma<<<grid, NTHREADS, SMEM_BYTES>>>(b1, W2a, b2a, W2b, b2b, out);
}

// round 12
// speedup vs baseline: 2.1668x; 2.1668x over previous
#include <cuda_runtime.h>
#include <cuda_fp16.h>
#include <math.h>
#include <stdint.h>

// ---------------- problem constants ----------------
#define BT      3136
#define NJ      43
#define NJ6     13
#define DLAT    512
#define OUTC    168

// ---------------- tiling ----------------
#define TM       128      // tokens per CTA
#define NCHUNK   128      // N per chunk (4 chunks)
#define KCH      64       // K per chunk (8 chunks)
#define NTHREADS 512      // 16 warps: 4 (m) x 4 (n), warp tile m32 n32

// ---------------- smem layout (bytes) ----------------
// A: 2 stages x 16K fp16           = 32768
// B: 2 stages x 16K fp16           = 32768
// b1s: 512 fp32                    = 2048
// w2t: [6][516] fp32               = 12384
// red: [4][128][8] fp32            = 16384
#define A_ST(b)  ((b)*16384)
#define OFF_B    32768
#define B_ST(b)  (OFF_B + (b)*16384)
#define OFF_B1   65536
#define OFF_W2T  67584
#define W2STR    516
#define OFF_RED  79968
#define SMEM_BYTES 96352

#define ASWZ(x) ((x) ^ (((x) >> 3) & 0x70))   // 128B rows
#define BSWZ(x) ((x) ^ (((x) >> 4) & 0x70))   // 256B rows

// ---------------- device scratch: preconverted fp16 ----------------
__device__ __half g_w1h[(size_t)NJ * DLAT * DLAT];
__device__ __half g_xh[(size_t)BT * NJ * DLAT];

__device__ __forceinline__ uint32_t smem_u32(const void* p) {
    uint32_t a;
    asm("{ .reg .u64 t; cvta.to.shared.u64 t, %1; cvt.u32.u64 %0, t; }" : "=r"(a) : "l"(p));
    return a;
}

__device__ __forceinline__ float gelu_erf(float v) {
    return 0.5f * v * (1.0f + erff(v * 0.70710678118654752f));
}

// pack two fp32 -> fp16x2 in a uint32 (same pattern as the proven bf16 pk())
__device__ __forceinline__ uint32_t pkh(float a, float b) {
    return (uint32_t)__half_as_ushort(__float2half_rn(a))
         | ((uint32_t)__half_as_ushort(__float2half_rn(b)) << 16);
}

// ---------------- cp.async ----------------
__device__ __forceinline__ void cpa16(uint32_t dst, const void* src, int ssz) {
    asm volatile("cp.async.cg.shared.global [%0], [%1], 16, %2;"
                 :: "r"(dst), "l"(src), "r"(ssz) : "memory");
}
#define CP_COMMIT() asm volatile("cp.async.commit_group;" ::: "memory")
#define CP_WAIT0()  asm volatile("cp.async.wait_group 0;" ::: "memory")

// ---------------- mma / ldmatrix ----------------
__device__ __forceinline__ void ldsm4(uint32_t* r, uint32_t addr) {
    asm volatile("ldmatrix.sync.aligned.m8n8.x4.shared.b16 {%0,%1,%2,%3}, [%4];"
                 : "=r"(r[0]), "=r"(r[1]), "=r"(r[2]), "=r"(r[3]) : "r"(addr));
}
__device__ __forceinline__ void ldsm4t(uint32_t* r, uint32_t addr) {
    asm volatile("ldmatrix.sync.aligned.m8n8.x4.trans.shared.b16 {%0,%1,%2,%3}, [%4];"
                 : "=r"(r[0]), "=r"(r[1]), "=r"(r[2]), "=r"(r[3]) : "r"(addr));
}
__device__ __forceinline__ void mma16816(float* c, const uint32_t* a, const uint32_t* b) {
    asm volatile("mma.sync.aligned.m16n8k16.row.col.f32.f16.f16.f32 "
                 "{%0,%1,%2,%3}, {%4,%5,%6,%7}, {%8,%9}, {%0,%1,%2,%3};"
                 : "+f"(c[0]), "+f"(c[1]), "+f"(c[2]), "+f"(c[3])
                 : "r"(a[0]), "r"(a[1]), "r"(a[2]), "r"(a[3]), "r"(b[0]), "r"(b[1]));
}

// ---------------- merged preconvert kernel (W1 then x) -> fp16 ----------------
#define W1F4 2818048u      // 43*512*512/4
#define XF4  17260544u     // 3136*43*512/4
__global__ __launch_bounds__(512, 2)
void convert_all_kernel(const float* __restrict__ W1, const float* __restrict__ x) {
    const uint32_t idx = blockIdx.x * 512u + threadIdx.x;   // exact grid: W1F4+XF4
    if (idx < W1F4) {
        const float4 v = ((const float4*)W1)[idx];
        uint2 o;
        o.x = pkh(v.x, v.y);
        o.y = pkh(v.z, v.w);
        ((uint2*)g_w1h)[idx] = o;
    } else {
        const uint32_t i2 = idx - W1F4;
        const float4 v = ((const float4*)x)[i2];
        uint2 o;
        o.x = pkh(v.x, v.y);
        o.y = pkh(v.z, v.w);
        ((uint2*)g_xh)[i2] = o;
    }
}

// ---------------- prefetch (fp16 gmem -> swizzled smem) ----------------
__device__ __forceinline__ void prefetch_a(uint32_t smb, int buf, int j, int tok0,
                                           int kc, int tid) {
    #pragma unroll
    for (int r = 0; r < 2; ++r) {
        const int idx = tid + r * NTHREADS;     // 0..1023
        const int m = idx >> 3, k8 = idx & 7;
        const int token = tok0 + m;
        const size_t g = ((size_t)token * NJ + j) * DLAT + kc * KCH + k8 * 8;
        const int ssz = (token < BT) ? 16 : 0;
        const uint32_t o = ASWZ((uint32_t)(m * 128 + k8 * 16));
        cpa16(smb + A_ST(buf) + o, g_xh + g, ssz);
    }
}
__device__ __forceinline__ void prefetch_b(uint32_t smb, int buf, int j, int kc,
                                           int nc, int tid) {
    const size_t base = (size_t)j * DLAT * DLAT + (size_t)(kc * KCH) * DLAT + nc * NCHUNK;
    #pragma unroll
    for (int r = 0; r < 2; ++r) {
        const int idx = tid + r * NTHREADS;     // 0..1023
        const int k = idx >> 4, n16 = idx & 15;
        const size_t g = base + (size_t)k * DLAT + n16 * 8;
        const uint32_t o = BSWZ((uint32_t)(k * 256 + n16 * 16));
        cpa16(smb + B_ST(buf) + o, g_w1h + g, 16);
    }
}

// ---------------- main kernel ----------------
__global__ __launch_bounds__(NTHREADS, 1)
void motion_decoder_mma(const float* __restrict__ b1,
                        const float* __restrict__ W2a,
                        const float* __restrict__ b2a,
                        const float* __restrict__ W2b,
                        const float* __restrict__ b2b,
                        float* __restrict__ out)
{
    extern __shared__ char sm[];
    const uint32_t smb = smem_u32(sm);
    const int tid = threadIdx.x;
    const int wid = tid >> 5, lane = tid & 31;
    const int wm = wid >> 2;               // 0..3 -> m offset wm*32
    const int wn = wid & 3;                // 0..3 -> n offset wn*32
    const int j = blockIdx.y;
    const int tok0 = blockIdx.x * TM;

    const int odim = (j < NJ6) ? 6 : 3;
    const float* W2 = (j < NJ6) ? (W2a + (size_t)j * DLAT * 6)
                                : (W2b + (size_t)(j - NJ6) * DLAT * 3);
    const float* b2 = (j < NJ6) ? (b2a + j * 6) : (b2b + (j - NJ6) * 3);
    const int colbase = (j < NJ6) ? j * 6 : (NJ6 * 6 + (j - NJ6) * 3);

    // pipeline prologue: stage 0 in flight
    prefetch_a(smb, 0, j, tok0, 0, tid);
    prefetch_b(smb, 0, j, 0, 0, tid);
    CP_COMMIT();

    // preload b1 and W2 (transposed to [o][n], zero-padded rows for odim==3)
    float* b1s = (float*)(sm + OFF_B1);
    for (int i = tid; i < DLAT; i += NTHREADS) b1s[i] = b1[j * DLAT + i];
    float* w2t = (float*)(sm + OFF_W2T);
    for (int i = tid; i < 6 * DLAT; i += NTHREADS) {
        const int o = i / DLAT, n = i - o * DLAT;
        w2t[o * W2STR + n] = (o < odim) ? W2[n * odim + o] : 0.f;
    }

    const int l15 = lane & 15;
    const int lhi = lane >> 4;

    // GEMM2 accumulators: [mt][rowhalf][o]
    float oacc[2][2][6];
    #pragma unroll
    for (int a = 0; a < 2; ++a)
        #pragma unroll
        for (int b = 0; b < 2; ++b)
            #pragma unroll
            for (int o = 0; o < 6; ++o) oacc[a][b][o] = 0.f;

    #pragma unroll 1
    for (int nc = 0; nc < 4; ++nc) {
        float c[2][4][4];
        #pragma unroll
        for (int mt = 0; mt < 2; ++mt)
            #pragma unroll
            for (int nt = 0; nt < 4; ++nt)
                #pragma unroll
                for (int q = 0; q < 4; ++q) c[mt][nt][q] = 0.f;

        #pragma unroll 1
        for (int kc = 0; kc < 8; ++kc) {
            const int s = nc * 8 + kc;
            CP_WAIT0();                    // stage s resident
            __syncthreads();               // visible; prior readers done

            if (s < 31) {                  // prefetch s+1 during MMA(s)
                const int s2 = s + 1;
                prefetch_a(smb, s2 & 1, j, tok0, s2 & 7, tid);
                prefetch_b(smb, s2 & 1, j, s2 & 7, s2 >> 3, tid);
                CP_COMMIT();
            }

            const int buf = s & 1;
            const uint32_t ab = smb + A_ST(buf);
            const uint32_t bb = smb + B_ST(buf);

            #pragma unroll
            for (int kt = 0; kt < 4; ++kt) {
                uint32_t ah[2][4], bh[2][4];
                #pragma unroll
                for (int mt = 0; mt < 2; ++mt) {
                    const int row = wm * 32 + mt * 16 + l15;
                    ldsm4(ah[mt], ab + ASWZ((uint32_t)(row * 128 + kt * 32 + lhi * 16)));
                }
                #pragma unroll
                for (int nt2 = 0; nt2 < 2; ++nt2) {
                    const int krow = kt * 16 + l15;
                    ldsm4t(bh[nt2], bb + BSWZ((uint32_t)(krow * 256 + wn * 64 + nt2 * 32 + lhi * 16)));
                }
                #pragma unroll
                for (int mt = 0; mt < 2; ++mt)
                    #pragma unroll
                    for (int nt = 0; nt < 4; ++nt)
                        mma16816(c[mt][nt], ah[mt], &bh[nt >> 1][(nt & 1) * 2]);
            }
        }

        // ---- fused epilogue: bias + GELU + GEMM2 partial, registers only ----
        #pragma unroll
        for (int nt = 0; nt < 4; ++nt) {
            const int ncol = wn * 32 + nt * 8 + (lane & 3) * 2;
            const int ng = nc * NCHUNK + ncol;
            const float bv0 = b1s[ng], bv1 = b1s[ng + 1];
            #pragma unroll
            for (int mt = 0; mt < 2; ++mt) {
                const float h0 = gelu_erf(c[mt][nt][0] + bv0);
                const float h1 = gelu_erf(c[mt][nt][1] + bv1);
                const float h2 = gelu_erf(c[mt][nt][2] + bv0);
                const float h3 = gelu_erf(c[mt][nt][3] + bv1);
                if (odim == 6) {
                    #pragma unroll
                    for (int o = 0; o < 6; ++o) {
                        const float w0 = w2t[o * W2STR + ng];
                        const float w1 = w2t[o * W2STR + ng + 1];
                        oacc[mt][0][o] += h0 * w0 + h1 * w1;
                        oacc[mt][1][o] += h2 * w0 + h3 * w1;
                    }
                } else {
                    #pragma unroll
                    for (int o = 0; o < 3; ++o) {
                        const float w0 = w2t[o * W2STR + ng];
                        const float w1 = w2t[o * W2STR + ng + 1];
                        oacc[mt][0][o] += h0 * w0 + h1 * w1;
                        oacc[mt][1][o] += h2 * w0 + h3 * w1;
                    }
                }
            }
        }
    }

    // ---- reduction: quad butterfly, then cross-warp via smem ----
    #pragma unroll
    for (int mt = 0; mt < 2; ++mt)
        #pragma unroll
        for (int i = 0; i < 2; ++i)
            #pragma unroll
            for (int o = 0; o < 6; ++o) {
                float v = oacc[mt][i][o];
                v += __shfl_xor_sync(0xffffffffu, v, 1);
                v += __shfl_xor_sync(0xffffffffu, v, 2);
                oacc[mt][i][o] = v;
            }

    float* red = (float*)(sm + OFF_RED);
    __syncthreads();                       // all MMA/epilogue done
    if ((lane & 3) == 0) {
        const int g = lane >> 2;
        #pragma unroll
        for (int mt = 0; mt < 2; ++mt)
            #pragma unroll
            for (int i = 0; i < 2; ++i) {
                const int row = wm * 32 + mt * 16 + i * 8 + g;
                #pragma unroll
                for (int o = 0; o < 6; ++o)
                    red[(wn * TM + row) * 8 + o] = oacc[mt][i][o];
            }
    }
    __syncthreads();

    #pragma unroll
    for (int p = 0; p < 2; ++p) {
        const int idx = tid + p * NTHREADS;
        if (idx < TM * odim) {
            const int m = idx / odim;
            const int o = idx - m * odim;
            const int token = tok0 + m;
            if (token < BT) {
                const float sdm = red[m * 8 + o] + red[(TM + m) * 8 + o]
                                + red[(2 * TM + m) * 8 + o] + red[(3 * TM + m) * 8 + o];
                out[(size_t)token * OUTC + colbase + o] = sdm + b2[o];
            }
        }
    }
}

extern "C" void kernel_launch(void* const* d_in, const int* in_sizes, int n_in,
                              void* d_out, int out_size)
{
    const float* x   = (const float*)d_in[0];
    const float* W1  = (const float*)d_in[1];
    const float* b1  = (const float*)d_in[2];
    const float* W2a = (const float*)d_in[3];
    const float* b2a = (const float*)d_in[4];
    const float* W2b = (const float*)d_in[5];
    const float* b2b = (const float*)d_in[6];
    float* out = (float*)d_out;

    // 1) preconvert W1 + x to fp16, single launch (exact grid)
    convert_all_kernel<<<(W1F4 + XF4) / 512, 512>>>(W1, x);

    // 2) fused fp16 GEMM
    cudaFuncSetAttribute(motion_decoder_mma,
                         cudaFuncAttributeMaxDynamicSharedMemorySize, SMEM_BYTES);
    dim3 grid((BT + TM - 1) / TM, NJ);          // 25 x 43
    motion_decoder_mma<<<grid, NTHREADS, SMEM_BYTES>>>(b1, W2a, b2a, W2b, b2b, out);
}

// round 13
// speedup vs baseline: 2.3603x; 1.0893x over previous
#include <cuda_runtime.h>
#include <cuda_fp16.h>
#include <math.h>
#include <stdint.h>

// ---------------- problem constants ----------------
#define BT      3136
#define NJ      43
#define NJ6     13
#define DLAT    512
#define OUTC    168

// ---------------- tiling ----------------
#define TM       128      // tokens per CTA
#define NCHUNK   128      // N per chunk (4 chunks)
#define KCH      128      // K per stage (4 k-stages)
#define NTHREADS 512      // 16 warps: 4 (m) x 4 (n), warp tile m32 n32

// ---------------- smem layout (bytes) ----------------
// A: 4 sub-tiles x 32K fp16 (resident, 256B-row BSWZ)  = 131072
// B: 2 stages x 32K fp16 (256B-row BSWZ)               = 65536
// b1s: 512 fp32                                        = 2048
// w2t: [6][516] fp32                                   = 12384
// red: [4][128][8] fp32 aliased onto B (dead at end)
#define OFF_A    0
#define A_SUB(k) ((k)*32768)
#define OFF_B    131072
#define B_ST(b)  (OFF_B + (b)*32768)
#define OFF_B1   196608
#define OFF_W2T  198656
#define W2STR    516
#define OFF_RED  OFF_B
#define SMEM_BYTES 211040

#define BSWZ(x) ((x) ^ (((x) >> 4) & 0x70))   // 256B rows: bits[4:6] ^= row&7

// ---------------- device scratch: preconverted fp16 ----------------
__device__ __half g_w1h[(size_t)NJ * DLAT * DLAT];
__device__ __half g_xh[(size_t)BT * NJ * DLAT];

__device__ __forceinline__ uint32_t smem_u32(const void* p) {
    uint32_t a;
    asm("{ .reg .u64 t; cvta.to.shared.u64 t, %1; cvt.u32.u64 %0, t; }" : "=r"(a) : "l"(p));
    return a;
}

__device__ __forceinline__ float gelu_erf(float v) {
    return 0.5f * v * (1.0f + erff(v * 0.70710678118654752f));
}

// pack two fp32 -> fp16x2 in a uint32
__device__ __forceinline__ uint32_t pkh(float a, float b) {
    return (uint32_t)__half_as_ushort(__float2half_rn(a))
         | ((uint32_t)__half_as_ushort(__float2half_rn(b)) << 16);
}

// ---------------- cp.async ----------------
__device__ __forceinline__ void cpa16(uint32_t dst, const void* src, int ssz) {
    asm volatile("cp.async.cg.shared.global [%0], [%1], 16, %2;"
                 :: "r"(dst), "l"(src), "r"(ssz) : "memory");
}
#define CP_COMMIT() asm volatile("cp.async.commit_group;" ::: "memory")
#define CP_WAIT0()  asm volatile("cp.async.wait_group 0;" ::: "memory")

// ---------------- mma / ldmatrix ----------------
__device__ __forceinline__ void ldsm4(uint32_t* r, uint32_t addr) {
    asm volatile("ldmatrix.sync.aligned.m8n8.x4.shared.b16 {%0,%1,%2,%3}, [%4];"
                 : "=r"(r[0]), "=r"(r[1]), "=r"(r[2]), "=r"(r[3]) : "r"(addr));
}
__device__ __forceinline__ void ldsm4t(uint32_t* r, uint32_t addr) {
    asm volatile("ldmatrix.sync.aligned.m8n8.x4.trans.shared.b16 {%0,%1,%2,%3}, [%4];"
                 : "=r"(r[0]), "=r"(r[1]), "=r"(r[2]), "=r"(r[3]) : "r"(addr));
}
__device__ __forceinline__ void mma16816(float* c, const uint32_t* a, const uint32_t* b) {
    asm volatile("mma.sync.aligned.m16n8k16.row.col.f32.f16.f16.f32 "
                 "{%0,%1,%2,%3}, {%4,%5,%6,%7}, {%8,%9}, {%0,%1,%2,%3};"
                 : "+f"(c[0]), "+f"(c[1]), "+f"(c[2]), "+f"(c[3])
                 : "r"(a[0]), "r"(a[1]), "r"(a[2]), "r"(a[3]), "r"(b[0]), "r"(b[1]));
}

// ---------------- merged preconvert kernel (W1 then x) -> fp16 ----------------
#define W1F4 2818048u      // 43*512*512/4
#define XF4  17260544u     // 3136*43*512/4
__global__ __launch_bounds__(512, 2)
void convert_all_kernel(const float* __restrict__ W1, const float* __restrict__ x) {
    const uint32_t idx = blockIdx.x * 512u + threadIdx.x;   // exact grid: W1F4+XF4
    if (idx < W1F4) {
        const float4 v = ((const float4*)W1)[idx];
        uint2 o;
        o.x = pkh(v.x, v.y);
        o.y = pkh(v.z, v.w);
        ((uint2*)g_w1h)[idx] = o;
    } else {
        const uint32_t i2 = idx - W1F4;
        const float4 v = ((const float4*)x)[i2];
        uint2 o;
        o.x = pkh(v.x, v.y);
        o.y = pkh(v.z, v.w);
        ((uint2*)g_xh)[i2] = o;
    }
}

// ---------------- prefetch (fp16 gmem -> swizzled smem) ----------------
// Entire A tile [128 tokens][512 K] as 4 sub-tiles of [128][128] (256B rows)
__device__ __forceinline__ void prefetch_a_all(uint32_t smb, int j, int tok0, int tid) {
    #pragma unroll
    for (int r = 0; r < 16; ++r) {
        const int idx = tid + r * NTHREADS;     // 0..8191
        const int m = idx >> 6;                 // token row
        const int c = idx & 63;                 // 16B unit within 1024B row
        const int kc = c >> 4, w = c & 15;
        const int token = tok0 + m;
        const size_t g = ((size_t)token * NJ + j) * DLAT + c * 8;
        const int ssz = (token < BT) ? 16 : 0;
        const uint32_t o = A_SUB(kc) + BSWZ((uint32_t)(m * 256 + w * 16));
        cpa16(smb + o, g_xh + g, ssz);
    }
}
// B stage: W1[j][kc*128 + 0..127][nc*128 + 0..127]
__device__ __forceinline__ void prefetch_b(uint32_t smb, int buf, int j, int nc,
                                           int kc, int tid) {
    const size_t base = (size_t)j * DLAT * DLAT + (size_t)(kc * KCH) * DLAT + nc * NCHUNK;
    #pragma unroll
    for (int r = 0; r < 4; ++r) {
        const int idx = tid + r * NTHREADS;     // 0..2047
        const int k = idx >> 4, n16 = idx & 15;
        const size_t g = base + (size_t)k * DLAT + n16 * 8;
        const uint32_t o = BSWZ((uint32_t)(k * 256 + n16 * 16));
        cpa16(smb + B_ST(buf) + o, g_w1h + g, 16);
    }
}

// ---------------- main kernel ----------------
__global__ __launch_bounds__(NTHREADS, 1)
void motion_decoder_mma(const float* __restrict__ b1,
                        const float* __restrict__ W2a,
                        const float* __restrict__ b2a,
                        const float* __restrict__ W2b,
                        const float* __restrict__ b2b,
                        float* __restrict__ out)
{
    extern __shared__ char sm[];
    const uint32_t smb = smem_u32(sm);
    const int tid = threadIdx.x;
    const int wid = tid >> 5, lane = tid & 31;
    const int wm = wid >> 2;               // 0..3 -> m offset wm*32
    const int wn = wid & 3;                // 0..3 -> n offset wn*32
    const int j = blockIdx.y;
    const int tok0 = blockIdx.x * TM;

    const int odim = (j < NJ6) ? 6 : 3;
    const float* W2 = (j < NJ6) ? (W2a + (size_t)j * DLAT * 6)
                                : (W2b + (size_t)(j - NJ6) * DLAT * 3);
    const float* b2 = (j < NJ6) ? (b2a + j * 6) : (b2b + (j - NJ6) * 3);
    const int colbase = (j < NJ6) ? j * 6 : (NJ6 * 6 + (j - NJ6) * 3);

    // prologue: full A + B stage 0 in flight
    prefetch_a_all(smb, j, tok0, tid);
    prefetch_b(smb, 0, j, 0, 0, tid);
    CP_COMMIT();

    // preload b1 and W2 (transposed to [o][n], zero-padded rows for odim==3)
    float* b1s = (float*)(sm + OFF_B1);
    for (int i = tid; i < DLAT; i += NTHREADS) b1s[i] = b1[j * DLAT + i];
    float* w2t = (float*)(sm + OFF_W2T);
    for (int i = tid; i < 6 * DLAT; i += NTHREADS) {
        const int o = i / DLAT, n = i - o * DLAT;
        w2t[o * W2STR + n] = (o < odim) ? W2[n * odim + o] : 0.f;
    }

    const int l15 = lane & 31 & 15;
    const int lhi = (lane >> 4) & 1;

    // precomputed swizzled fragment offsets (hoisted out of all loops)
    uint32_t aoffp[2], boffp[2];
    #pragma unroll
    for (int mt = 0; mt < 2; ++mt) {
        const int row = wm * 32 + mt * 16 + l15;
        aoffp[mt] = BSWZ((uint32_t)(row * 256 + lhi * 16));
    }
    #pragma unroll
    for (int nt2 = 0; nt2 < 2; ++nt2)
        boffp[nt2] = BSWZ((uint32_t)(l15 * 256 + wn * 64 + nt2 * 32 + lhi * 16));

    // GEMM2 accumulators: [mt][rowhalf][o]
    float oacc[2][2][6];
    #pragma unroll
    for (int a = 0; a < 2; ++a)
        #pragma unroll
        for (int b = 0; b < 2; ++b)
            #pragma unroll
            for (int o = 0; o < 6; ++o) oacc[a][b][o] = 0.f;

    #pragma unroll 1
    for (int nc = 0; nc < 4; ++nc) {
        float c[2][4][4];
        #pragma unroll
        for (int mt = 0; mt < 2; ++mt)
            #pragma unroll
            for (int nt = 0; nt < 4; ++nt)
                #pragma unroll
                for (int q = 0; q < 4; ++q) c[mt][nt][q] = 0.f;

        #pragma unroll 1
        for (int kc = 0; kc < 4; ++kc) {
            const int s = nc * 4 + kc;
            CP_WAIT0();                    // stage s B (and A on s=0) resident
            __syncthreads();               // visible; prior readers of buf done

            if (s < 15) {                  // prefetch B(s+1) during MMA(s)
                const int s2 = s + 1;
                prefetch_b(smb, s2 & 1, j, s2 >> 2, s2 & 3, tid);
                CP_COMMIT();
            }

            const uint32_t ab = smb + A_SUB(kc);
            const uint32_t bb = smb + B_ST(s & 1);

            #pragma unroll
            for (int kt = 0; kt < 8; ++kt) {
                uint32_t ah[2][4], bh[2][4];
                #pragma unroll
                for (int mt = 0; mt < 2; ++mt)
                    ldsm4(ah[mt], ab + (aoffp[mt] ^ (uint32_t)(kt * 32)));
                #pragma unroll
                for (int nt2 = 0; nt2 < 2; ++nt2)
                    ldsm4t(bh[nt2], bb + boffp[nt2] + ((uint32_t)kt << 12));
                #pragma unroll
                for (int mt = 0; mt < 2; ++mt)
                    #pragma unroll
                    for (int nt = 0; nt < 4; ++nt)
                        mma16816(c[mt][nt], ah[mt], &bh[nt >> 1][(nt & 1) * 2]);
            }
        }

        // ---- fused epilogue: bias + GELU + GEMM2 partial, registers only ----
        #pragma unroll
        for (int nt = 0; nt < 4; ++nt) {
            const int ncol = wn * 32 + nt * 8 + (lane & 3) * 2;
            const int ng = nc * NCHUNK + ncol;
            const float bv0 = b1s[ng], bv1 = b1s[ng + 1];
            #pragma unroll
            for (int mt = 0; mt < 2; ++mt) {
                const float h0 = gelu_erf(c[mt][nt][0] + bv0);
                const float h1 = gelu_erf(c[mt][nt][1] + bv1);
                const float h2 = gelu_erf(c[mt][nt][2] + bv0);
                const float h3 = gelu_erf(c[mt][nt][3] + bv1);
                if (odim == 6) {
                    #pragma unroll
                    for (int o = 0; o < 6; ++o) {
                        const float w0 = w2t[o * W2STR + ng];
                        const float w1 = w2t[o * W2STR + ng + 1];
                        oacc[mt][0][o] += h0 * w0 + h1 * w1;
                        oacc[mt][1][o] += h2 * w0 + h3 * w1;
                    }
                } else {
                    #pragma unroll
                    for (int o = 0; o < 3; ++o) {
                        const float w0 = w2t[o * W2STR + ng];
                        const float w1 = w2t[o * W2STR + ng + 1];
                        oacc[mt][0][o] += h0 * w0 + h1 * w1;
                        oacc[mt][1][o] += h2 * w0 + h3 * w1;
                    }
                }
            }
        }
    }

    // ---- reduction: quad butterfly, then cross-warp via smem (aliased on B) ----
    #pragma unroll
    for (int mt = 0; mt < 2; ++mt)
        #pragma unroll
        for (int i = 0; i < 2; ++i)
            #pragma unroll
            for (int o = 0; o < 6; ++o) {
                float v = oacc[mt][i][o];
                v += __shfl_xor_sync(0xffffffffu, v, 1);
                v += __shfl_xor_sync(0xffffffffu, v, 2);
                oacc[mt][i][o] = v;
            }

    float* red = (float*)(sm + OFF_RED);
    __syncthreads();                       // all MMA done; no cp.async pending
    if ((lane & 3) == 0) {
        const int g = lane >> 2;
        #pragma unroll
        for (int mt = 0; mt < 2; ++mt)
            #pragma unroll
            for (int i = 0; i < 2; ++i) {
                const int row = wm * 32 + mt * 16 + i * 8 + g;
                #pragma unroll
                for (int o = 0; o < 6; ++o)
                    red[(wn * TM + row) * 8 + o] = oacc[mt][i][o];
            }
    }
    __syncthreads();

    #pragma unroll
    for (int p = 0; p < 2; ++p) {
        const int idx = tid + p * NTHREADS;
        if (idx < TM * odim) {
            const int m = idx / odim;
            const int o = idx - m * odim;
            const int token = tok0 + m;
            if (token < BT) {
                const float sdm = red[m * 8 + o] + red[(TM + m) * 8 + o]
                                + red[(2 * TM + m) * 8 + o] + red[(3 * TM + m) * 8 + o];
                out[(size_t)token * OUTC + colbase + o] = sdm + b2[o];
            }
        }
    }
}

extern "C" void kernel_launch(void* const* d_in, const int* in_sizes, int n_in,
                              void* d_out, int out_size)
{
    const float* x   = (const float*)d_in[0];
    const float* W1  = (const float*)d_in[1];
    const float* b1  = (const float*)d_in[2];
    const float* W2a = (const float*)d_in[3];
    const float* b2a = (const float*)d_in[4];
    const float* W2b = (const float*)d_in[5];
    const float* b2b = (const float*)d_in[6];
    float* out = (float*)d_out;

    // 1) preconvert W1 + x to fp16, single launch (exact grid)
    convert_all_kernel<<<(W1F4 + XF4) / 512, 512>>>(W1, x);

    // 2) fused fp16 GEMM: A resident, 16 B-stages
    cudaFuncSetAttribute(motion_decoder_mma,
                         cudaFuncAttributeMaxDynamicSharedMemorySize, SMEM_BYTES);
    dim3 grid((BT + TM - 1) / TM, NJ);          // 25 x 43
    motion_decoder_mma<<<grid, NTHREADS, SMEM_BYTES>>>(b1, W2a, b2a, W2b, b2b, out);
}

// round 14
// speedup vs baseline: 2.5983x; 1.1008x over previous
#include <cuda_runtime.h>
#include <cuda_fp16.h>
#include <math.h>
#include <stdint.h>

// ---------------- problem constants ----------------
#define BT      3136
#define NJ      43
#define NJ6     13
#define DLAT    512
#define OUTC    168

// ---------------- tiling ----------------
#define TM       64       // tokens per CTA
#define NCHUNK   128      // N per chunk (4 chunks)
#define KCH      64       // K per B stage (8 k-stages per chunk)
#define NTHREADS 256      // 8 warps: 2 (m) x 4 (n), warp tile m32 n32

// ---------------- smem layout (bytes), 2 CTAs/SM ----------------
// A: 4 sub-tiles x 16K fp16 (resident, 256B-row BSWZ)  = 65536
// B: 2 stages x 16K fp16 (256B-row BSWZ)               = 32768
// b1s: 512 fp32                                        = 2048
// w2t: [6][516] fp32                                   = 12384
// red: [4][64][8] fp32 aliased onto B (dead at end)
#define OFF_A    0
#define A_SUB(k) ((k)*16384)
#define OFF_B    65536
#define B_ST(b)  (OFF_B + (b)*16384)
#define OFF_B1   98304
#define OFF_W2T  100352
#define W2STR    516
#define OFF_RED  OFF_B
#define SMEM_BYTES 112736

#define BSWZ(x) ((x) ^ (((x) >> 4) & 0x70))   // 256B rows: bits[4:6] ^= row&7

// ---------------- device scratch: preconverted fp16 ----------------
__device__ __half g_w1h[(size_t)NJ * DLAT * DLAT];
__device__ __half g_xh[(size_t)BT * NJ * DLAT];

__device__ __forceinline__ uint32_t smem_u32(const void* p) {
    uint32_t a;
    asm("{ .reg .u64 t; cvta.to.shared.u64 t, %1; cvt.u32.u64 %0, t; }" : "=r"(a) : "l"(p));
    return a;
}

__device__ __forceinline__ float gelu_erf(float v) {
    return 0.5f * v * (1.0f + erff(v * 0.70710678118654752f));
}

// pack two fp32 -> fp16x2 in a uint32
__device__ __forceinline__ uint32_t pkh(float a, float b) {
    return (uint32_t)__half_as_ushort(__float2half_rn(a))
         | ((uint32_t)__half_as_ushort(__float2half_rn(b)) << 16);
}

// ---------------- cp.async ----------------
__device__ __forceinline__ void cpa16(uint32_t dst, const void* src, int ssz) {
    asm volatile("cp.async.cg.shared.global [%0], [%1], 16, %2;"
                 :: "r"(dst), "l"(src), "r"(ssz) : "memory");
}
#define CP_COMMIT() asm volatile("cp.async.commit_group;" ::: "memory")
#define CP_WAIT0()  asm volatile("cp.async.wait_group 0;" ::: "memory")

// ---------------- mma / ldmatrix ----------------
__device__ __forceinline__ void ldsm4(uint32_t* r, uint32_t addr) {
    asm volatile("ldmatrix.sync.aligned.m8n8.x4.shared.b16 {%0,%1,%2,%3}, [%4];"
                 : "=r"(r[0]), "=r"(r[1]), "=r"(r[2]), "=r"(r[3]) : "r"(addr));
}
__device__ __forceinline__ void ldsm4t(uint32_t* r, uint32_t addr) {
    asm volatile("ldmatrix.sync.aligned.m8n8.x4.trans.shared.b16 {%0,%1,%2,%3}, [%4];"
                 : "=r"(r[0]), "=r"(r[1]), "=r"(r[2]), "=r"(r[3]) : "r"(addr));
}
__device__ __forceinline__ void mma16816(float* c, const uint32_t* a, const uint32_t* b) {
    asm volatile("mma.sync.aligned.m16n8k16.row.col.f32.f16.f16.f32 "
                 "{%0,%1,%2,%3}, {%4,%5,%6,%7}, {%8,%9}, {%0,%1,%2,%3};"
                 : "+f"(c[0]), "+f"(c[1]), "+f"(c[2]), "+f"(c[3])
                 : "r"(a[0]), "r"(a[1]), "r"(a[2]), "r"(a[3]), "r"(b[0]), "r"(b[1]));
}

// ---------------- merged preconvert kernel (W1 then x) -> fp16 ----------------
#define W1F4 2818048u      // 43*512*512/4
#define XF4  17260544u     // 3136*43*512/4
__global__ __launch_bounds__(512, 2)
void convert_all_kernel(const float* __restrict__ W1, const float* __restrict__ x) {
    const uint32_t idx = blockIdx.x * 512u + threadIdx.x;   // exact grid: W1F4+XF4
    if (idx < W1F4) {
        const float4 v = ((const float4*)W1)[idx];
        uint2 o;
        o.x = pkh(v.x, v.y);
        o.y = pkh(v.z, v.w);
        ((uint2*)g_w1h)[idx] = o;
    } else {
        const uint32_t i2 = idx - W1F4;
        const float4 v = ((const float4*)x)[i2];
        uint2 o;
        o.x = pkh(v.x, v.y);
        o.y = pkh(v.z, v.w);
        ((uint2*)g_xh)[i2] = o;
    }
}

// ---------------- prefetch (fp16 gmem -> swizzled smem) ----------------
// Entire A tile [64 tokens][512 K] as 4 sub-tiles of [64][128] (256B rows)
__device__ __forceinline__ void prefetch_a_all(uint32_t smb, int j, int tok0, int tid) {
    #pragma unroll
    for (int r = 0; r < 16; ++r) {
        const int idx = tid + r * NTHREADS;     // 0..4095
        const int m = idx >> 6;                 // token row (0..63)
        const int c = idx & 63;                 // 16B unit within 1024B of K
        const int sub = c >> 4, w = c & 15;
        const int token = tok0 + m;
        const size_t g = ((size_t)token * NJ + j) * DLAT + c * 8;
        const int ssz = (token < BT) ? 16 : 0;
        const uint32_t o = A_SUB(sub) + BSWZ((uint32_t)(m * 256 + w * 16));
        cpa16(smb + o, g_xh + g, ssz);
    }
}
// B stage: W1[j][kc*64 + 0..63][nc*128 + 0..127]
__device__ __forceinline__ void prefetch_b(uint32_t smb, int buf, int j, int nc,
                                           int kc, int tid) {
    const size_t base = (size_t)j * DLAT * DLAT + (size_t)(kc * KCH) * DLAT + nc * NCHUNK;
    #pragma unroll
    for (int r = 0; r < 4; ++r) {
        const int idx = tid + r * NTHREADS;     // 0..1023
        const int k = idx >> 4, n16 = idx & 15;
        const size_t g = base + (size_t)k * DLAT + n16 * 8;
        const uint32_t o = BSWZ((uint32_t)(k * 256 + n16 * 16));
        cpa16(smb + B_ST(buf) + o, g_w1h + g, 16);
    }
}

// ---------------- main kernel ----------------
__global__ __launch_bounds__(NTHREADS, 2)
void motion_decoder_mma(const float* __restrict__ b1,
                        const float* __restrict__ W2a,
                        const float* __restrict__ b2a,
                        const float* __restrict__ W2b,
                        const float* __restrict__ b2b,
                        float* __restrict__ out)
{
    extern __shared__ char sm[];
    const uint32_t smb = smem_u32(sm);
    const int tid = threadIdx.x;
    const int wid = tid >> 5, lane = tid & 31;
    const int wm = wid >> 2;               // 0..1 -> m offset wm*32
    const int wn = wid & 3;                // 0..3 -> n offset wn*32
    const int j = blockIdx.y;
    const int tok0 = blockIdx.x * TM;

    const int odim = (j < NJ6) ? 6 : 3;
    const float* W2 = (j < NJ6) ? (W2a + (size_t)j * DLAT * 6)
                                : (W2b + (size_t)(j - NJ6) * DLAT * 3);
    const float* b2 = (j < NJ6) ? (b2a + j * 6) : (b2b + (j - NJ6) * 3);
    const int colbase = (j < NJ6) ? j * 6 : (NJ6 * 6 + (j - NJ6) * 3);

    // prologue: full A + B stage 0 in flight
    prefetch_a_all(smb, j, tok0, tid);
    prefetch_b(smb, 0, j, 0, 0, tid);
    CP_COMMIT();

    // preload b1 and W2 (transposed to [o][n], zero-padded rows for odim==3)
    float* b1s = (float*)(sm + OFF_B1);
    for (int i = tid; i < DLAT; i += NTHREADS) b1s[i] = b1[j * DLAT + i];
    float* w2t = (float*)(sm + OFF_W2T);
    for (int i = tid; i < 6 * DLAT; i += NTHREADS) {
        const int o = i / DLAT, n = i - o * DLAT;
        w2t[o * W2STR + n] = (o < odim) ? W2[n * odim + o] : 0.f;
    }

    const int l15 = lane & 15;
    const int lhi = (lane >> 4) & 1;

    // precomputed swizzled fragment offsets (hoisted out of all loops)
    uint32_t aoffp[2], boffp[2];
    #pragma unroll
    for (int mt = 0; mt < 2; ++mt) {
        const int row = wm * 32 + mt * 16 + l15;
        aoffp[mt] = BSWZ((uint32_t)(row * 256 + lhi * 16));
    }
    #pragma unroll
    for (int nt2 = 0; nt2 < 2; ++nt2)
        boffp[nt2] = BSWZ((uint32_t)(l15 * 256 + wn * 64 + nt2 * 32 + lhi * 16));

    // GEMM2 accumulators: [mt][rowhalf][o]
    float oacc[2][2][6];
    #pragma unroll
    for (int a = 0; a < 2; ++a)
        #pragma unroll
        for (int b = 0; b < 2; ++b)
            #pragma unroll
            for (int o = 0; o < 6; ++o) oacc[a][b][o] = 0.f;

    #pragma unroll 1
    for (int nc = 0; nc < 4; ++nc) {
        float c[2][4][4];
        #pragma unroll
        for (int mt = 0; mt < 2; ++mt)
            #pragma unroll
            for (int nt = 0; nt < 4; ++nt)
                #pragma unroll
                for (int q = 0; q < 4; ++q) c[mt][nt][q] = 0.f;

        #pragma unroll 1
        for (int kc = 0; kc < 8; ++kc) {
            const int s = nc * 8 + kc;
            CP_WAIT0();                    // stage s B (and A on s=0) resident
            __syncthreads();               // visible; prior readers of buf done

            if (s < 31) {                  // prefetch B(s+1) during MMA(s)
                const int s2 = s + 1;
                prefetch_b(smb, s2 & 1, j, s2 >> 3, s2 & 7, tid);
                CP_COMMIT();
            }

            const uint32_t bb = smb + B_ST(s & 1);

            #pragma unroll
            for (int kt = 0; kt < 4; ++kt) {
                const int kg = kc * 4 + kt;          // global k16 index 0..31
                const uint32_t ab = smb + A_SUB(kg >> 3);
                const uint32_t ainner = (uint32_t)((kg & 7) * 32);
                uint32_t ah[2][4], bh[2][4];
                #pragma unroll
                for (int mt = 0; mt < 2; ++mt)
                    ldsm4(ah[mt], ab + (aoffp[mt] ^ ainner));
                #pragma unroll
                for (int nt2 = 0; nt2 < 2; ++nt2)
                    ldsm4t(bh[nt2], bb + boffp[nt2] + ((uint32_t)kt << 12));
                #pragma unroll
                for (int mt = 0; mt < 2; ++mt)
                    #pragma unroll
                    for (int nt = 0; nt < 4; ++nt)
                        mma16816(c[mt][nt], ah[mt], &bh[nt >> 1][(nt & 1) * 2]);
            }
        }

        // ---- fused epilogue: bias + GELU + GEMM2 partial, registers only ----
        #pragma unroll
        for (int nt = 0; nt < 4; ++nt) {
            const int ncol = wn * 32 + nt * 8 + (lane & 3) * 2;
            const int ng = nc * NCHUNK + ncol;
            const float bv0 = b1s[ng], bv1 = b1s[ng + 1];
            #pragma unroll
            for (int mt = 0; mt < 2; ++mt) {
                const float h0 = gelu_erf(c[mt][nt][0] + bv0);
                const float h1 = gelu_erf(c[mt][nt][1] + bv1);
                const float h2 = gelu_erf(c[mt][nt][2] + bv0);
                const float h3 = gelu_erf(c[mt][nt][3] + bv1);
                if (odim == 6) {
                    #pragma unroll
                    for (int o = 0; o < 6; ++o) {
                        const float w0 = w2t[o * W2STR + ng];
                        const float w1 = w2t[o * W2STR + ng + 1];
                        oacc[mt][0][o] += h0 * w0 + h1 * w1;
                        oacc[mt][1][o] += h2 * w0 + h3 * w1;
                    }
                } else {
                    #pragma unroll
                    for (int o = 0; o < 3; ++o) {
                        const float w0 = w2t[o * W2STR + ng];
                        const float w1 = w2t[o * W2STR + ng + 1];
                        oacc[mt][0][o] += h0 * w0 + h1 * w1;
                        oacc[mt][1][o] += h2 * w0 + h3 * w1;
                    }
                }
            }
        }
    }

    // ---- reduction: quad butterfly, then cross-warp via smem (aliased on B) ----
    #pragma unroll
    for (int mt = 0; mt < 2; ++mt)
        #pragma unroll
        for (int i = 0; i < 2; ++i)
            #pragma unroll
            for (int o = 0; o < 6; ++o) {
                float v = oacc[mt][i][o];
                v += __shfl_xor_sync(0xffffffffu, v, 1);
                v += __shfl_xor_sync(0xffffffffu, v, 2);
                oacc[mt][i][o] = v;
            }

    float* red = (float*)(sm + OFF_RED);
    __syncthreads();                       // all MMA done; no cp.async pending
    if ((lane & 3) == 0) {
        const int g = lane >> 2;
        #pragma unroll
        for (int mt = 0; mt < 2; ++mt)
            #pragma unroll
            for (int i = 0; i < 2; ++i) {
                const int row = wm * 32 + mt * 16 + i * 8 + g;
                #pragma unroll
                for (int o = 0; o < 6; ++o)
                    red[(wn * TM + row) * 8 + o] = oacc[mt][i][o];
            }
    }
    __syncthreads();

    #pragma unroll
    for (int p = 0; p < 2; ++p) {
        const int idx = tid + p * NTHREADS;
        if (idx < TM * odim) {
            const int m = idx / odim;
            const int o = idx - m * odim;
            const int token = tok0 + m;
            if (token < BT) {
                const float sdm = red[m * 8 + o] + red[(TM + m) * 8 + o]
                                + red[(2 * TM + m) * 8 + o] + red[(3 * TM + m) * 8 + o];
                out[(size_t)token * OUTC + colbase + o] = sdm + b2[o];
            }
        }
    }
}

extern "C" void kernel_launch(void* const* d_in, const int* in_sizes, int n_in,
                              void* d_out, int out_size)
{
    const float* x   = (const float*)d_in[0];
    const float* W1  = (const float*)d_in[1];
    const float* b1  = (const float*)d_in[2];
    const float* W2a = (const float*)d_in[3];
    const float* b2a = (const float*)d_in[4];
    const float* W2b = (const float*)d_in[5];
    const float* b2b = (const float*)d_in[6];
    float* out = (float*)d_out;

    // 1) preconvert W1 + x to fp16, single launch (exact grid)
    convert_all_kernel<<<(W1F4 + XF4) / 512, 512>>>(W1, x);

    // 2) fused fp16 GEMM: A resident, 2 CTAs/SM
    cudaFuncSetAttribute(motion_decoder_mma,
                         cudaFuncAttributeMaxDynamicSharedMemorySize, SMEM_BYTES);
    dim3 grid((BT + TM - 1) / TM, NJ);          // 49 x 43
    motion_decoder_mma<<<grid, NTHREADS, SMEM_BYTES>>>(b1, W2a, b2a, W2b, b2b, out);
}

// round 15
// speedup vs baseline: 2.6232x; 1.0096x over previous
#include <cuda_runtime.h>
#include <cuda_fp16.h>
#include <math.h>
#include <stdint.h>

// ---------------- problem constants ----------------
#define BT      3136
#define NJ      43
#define NJ6     13
#define DLAT    512
#define OUTC    168

// ---------------- tiling ----------------
#define TM       64       // tokens per CTA
#define NCHUNK   128      // N per chunk (4 chunks)
#define KCH      64       // K per B stage (8 k-stages per chunk)
#define NTHREADS 256      // 8 warps: 2 (m) x 4 (n), warp tile m32 n32

// ---------------- smem layout (bytes), 2 CTAs/SM ----------------
#define OFF_A    0
#define A_SUB(k) ((k)*16384)               // 4 x [64][128] fp16, 256B-row BSWZ
#define OFF_B    65536
#define B_ST(b)  (OFF_B + (b)*16384)       // 2 stages x [64][128] fp16
#define OFF_B1   98304                     // 512 fp32
#define OFF_W2T  100352                    // [6][516] fp32
#define W2STR    516
#define OFF_RED  OFF_B                     // aliased (B dead at end)
#define SMEM_BYTES 112736

#define BSWZ(x) ((x) ^ (((x) >> 4) & 0x70))   // 256B rows: bits[4:6] ^= row&7

// ---------------- device scratch: preconverted fp16 ----------------
__device__ __half g_w1h[(size_t)NJ * DLAT * DLAT];
__device__ __half g_xh[(size_t)BT * NJ * DLAT];

__device__ __forceinline__ uint32_t smem_u32(const void* p) {
    uint32_t a;
    asm("{ .reg .u64 t; cvta.to.shared.u64 t, %1; cvt.u32.u64 %0, t; }" : "=r"(a) : "l"(p));
    return a;
}

__device__ __forceinline__ float gelu_erf(float v) {
    return 0.5f * v * (1.0f + erff(v * 0.70710678118654752f));
}

__device__ __forceinline__ uint32_t pkh(float a, float b) {
    return (uint32_t)__half_as_ushort(__float2half_rn(a))
         | ((uint32_t)__half_as_ushort(__float2half_rn(b)) << 16);
}

// ---------------- cp.async ----------------
__device__ __forceinline__ void cpa16(uint32_t dst, const void* src, int ssz) {
    asm volatile("cp.async.cg.shared.global [%0], [%1], 16, %2;"
                 :: "r"(dst), "l"(src), "r"(ssz) : "memory");
}
#define CP_COMMIT() asm volatile("cp.async.commit_group;" ::: "memory")
#define CP_WAIT0()  asm volatile("cp.async.wait_group 0;" ::: "memory")

// ---------------- mma / ldmatrix ----------------
__device__ __forceinline__ void ldsm4(uint32_t* r, uint32_t addr) {
    asm volatile("ldmatrix.sync.aligned.m8n8.x4.shared.b16 {%0,%1,%2,%3}, [%4];"
                 : "=r"(r[0]), "=r"(r[1]), "=r"(r[2]), "=r"(r[3]) : "r"(addr));
}
__device__ __forceinline__ void ldsm4t(uint32_t* r, uint32_t addr) {
    asm volatile("ldmatrix.sync.aligned.m8n8.x4.trans.shared.b16 {%0,%1,%2,%3}, [%4];"
                 : "=r"(r[0]), "=r"(r[1]), "=r"(r[2]), "=r"(r[3]) : "r"(addr));
}
__device__ __forceinline__ void mma16816(float* c, const uint32_t* a, const uint32_t* b) {
    asm volatile("mma.sync.aligned.m16n8k16.row.col.f32.f16.f16.f32 "
                 "{%0,%1,%2,%3}, {%4,%5,%6,%7}, {%8,%9}, {%0,%1,%2,%3};"
                 : "+f"(c[0]), "+f"(c[1]), "+f"(c[2]), "+f"(c[3])
                 : "r"(a[0]), "r"(a[1]), "r"(a[2]), "r"(a[3]), "r"(b[0]), "r"(b[1]));
}

// ---------------- merged preconvert kernel (W1 then x) -> fp16 ----------------
#define W1F4 2818048u      // 43*512*512/4
#define XF4  17260544u     // 3136*43*512/4
__global__ __launch_bounds__(512, 2)
void convert_all_kernel(const float* __restrict__ W1, const float* __restrict__ x) {
    const uint32_t idx = blockIdx.x * 512u + threadIdx.x;   // exact grid: W1F4+XF4
    if (idx < W1F4) {
        const float4 v = ((const float4*)W1)[idx];
        uint2 o;
        o.x = pkh(v.x, v.y);
        o.y = pkh(v.z, v.w);
        ((uint2*)g_w1h)[idx] = o;
    } else {
        const uint32_t i2 = idx - W1F4;
        const float4 v = ((const float4*)x)[i2];
        uint2 o;
        o.x = pkh(v.x, v.y);
        o.y = pkh(v.z, v.w);
        ((uint2*)g_xh)[i2] = o;
    }
}

// ---------------- A prefetch (runs once) ----------------
__device__ __forceinline__ void prefetch_a_all(uint32_t smb, int j, int tok0, int tid) {
    #pragma unroll
    for (int r = 0; r < 16; ++r) {
        const int idx = tid + r * NTHREADS;     // 0..4095
        const int m = idx >> 6;                 // token row (0..63)
        const int c = idx & 63;                 // 16B unit of K
        const int sub = c >> 4, w = c & 15;
        const int token = tok0 + m;
        const size_t g = ((size_t)token * NJ + j) * DLAT + c * 8;
        const int ssz = (token < BT) ? 16 : 0;
        const uint32_t o = A_SUB(sub) + BSWZ((uint32_t)(m * 256 + w * 16));
        cpa16(smb + o, g_xh + g, ssz);
    }
}

// ---------------- main kernel ----------------
__global__ __launch_bounds__(NTHREADS, 2)
void motion_decoder_mma(const float* __restrict__ b1,
                        const float* __restrict__ W2a,
                        const float* __restrict__ b2a,
                        const float* __restrict__ W2b,
                        const float* __restrict__ b2b,
                        float* __restrict__ out)
{
    extern __shared__ char sm[];
    const uint32_t smb = smem_u32(sm);
    const int tid = threadIdx.x;
    const int wid = tid >> 5, lane = tid & 31;
    const int wm = wid >> 2;               // 0..1 -> m offset wm*32
    const int wn = wid & 3;                // 0..3 -> n offset wn*32
    const int j = blockIdx.y;
    const int tok0 = blockIdx.x * TM;

    const int odim = (j < NJ6) ? 6 : 3;
    const float* W2 = (j < NJ6) ? (W2a + (size_t)j * DLAT * 6)
                                : (W2b + (size_t)(j - NJ6) * DLAT * 3);
    const float* b2 = (j < NJ6) ? (b2a + j * 6) : (b2b + (j - NJ6) * 3);
    const int colbase = (j < NJ6) ? j * 6 : (NJ6 * 6 + (j - NJ6) * 3);

    // ---- B prefetch incremental state (hoisted address math) ----
    // idx_r = tid + r*256 -> k = k0 + 16r, n16 fixed.
    // smem: BSWZ(k*256 + n16*16) = o0 + 4096*r   (XOR mask invariant in r)
    // gmem: base + k*DLAT + n16*8 = p + r*16*DLAT
    const int k0 = tid >> 4, n16 = tid & 15;
    const uint32_t bo0 = BSWZ((uint32_t)(k0 * 256 + n16 * 16));
    const __half* bp = g_w1h + (size_t)j * DLAT * DLAT + (size_t)k0 * DLAT + n16 * 8;

    // prologue: full A + B stage 0 in flight
    prefetch_a_all(smb, j, tok0, tid);
    {
        const uint32_t d = smb + B_ST(0) + bo0;
        cpa16(d,            bp,               16);
        cpa16(d + 4096,     bp + 16 * DLAT,   16);
        cpa16(d + 8192,     bp + 32 * DLAT,   16);
        cpa16(d + 12288,    bp + 48 * DLAT,   16);
        bp += 64 * DLAT;   // advance to stage 1 (t=0, no wrap)
    }
    CP_COMMIT();

    // preload b1 and W2 (transposed to [o][n], zero-padded rows for odim==3)
    float* b1s = (float*)(sm + OFF_B1);
    for (int i = tid; i < DLAT; i += NTHREADS) b1s[i] = b1[j * DLAT + i];
    float* w2t = (float*)(sm + OFF_W2T);
    for (int i = tid; i < 6 * DLAT; i += NTHREADS) {
        const int o = i / DLAT, n = i - o * DLAT;
        w2t[o * W2STR + n] = (o < odim) ? W2[n * odim + o] : 0.f;
    }

    const int l15 = lane & 15;
    const int lhi = (lane >> 4) & 1;

    // precomputed swizzled fragment offsets (hoisted)
    uint32_t aoffp[2], boffp[2];
    #pragma unroll
    for (int mt = 0; mt < 2; ++mt) {
        const int row = wm * 32 + mt * 16 + l15;
        aoffp[mt] = BSWZ((uint32_t)(row * 256 + lhi * 16));
    }
    #pragma unroll
    for (int nt2 = 0; nt2 < 2; ++nt2)
        boffp[nt2] = BSWZ((uint32_t)(l15 * 256 + wn * 64 + nt2 * 32 + lhi * 16));

    // GEMM2 accumulators: [mt][rowhalf][o]
    float oacc[2][2][6];
    #pragma unroll
    for (int a = 0; a < 2; ++a)
        #pragma unroll
        for (int b = 0; b < 2; ++b)
            #pragma unroll
            for (int o = 0; o < 6; ++o) oacc[a][b][o] = 0.f;

    #pragma unroll 1
    for (int nc = 0; nc < 4; ++nc) {
        float c[2][4][4];
        #pragma unroll
        for (int mt = 0; mt < 2; ++mt)
            #pragma unroll
            for (int nt = 0; nt < 4; ++nt)
                #pragma unroll
                for (int q = 0; q < 4; ++q) c[mt][nt][q] = 0.f;

        #pragma unroll 1
        for (int kc = 0; kc < 8; ++kc) {
            const int s = nc * 8 + kc;
            CP_WAIT0();                    // stage s B (and A on s=0) resident
            __syncthreads();               // visible; prior readers of buf done

            if (s < 31) {                  // prefetch B(s+1) during MMA(s)
                const int t = s + 1;
                const uint32_t d = smb + B_ST(t & 1) + bo0;
                cpa16(d,         bp,             16);
                cpa16(d + 4096,  bp + 16 * DLAT, 16);
                cpa16(d + 8192,  bp + 32 * DLAT, 16);
                cpa16(d + 12288, bp + 48 * DLAT, 16);
                CP_COMMIT();
                bp += 64 * DLAT;
                if ((t & 7) == 7) bp += 128 - 512 * DLAT;   // nc wrap
            }

            const uint32_t bb = smb + B_ST(s & 1);

            #pragma unroll
            for (int kt = 0; kt < 4; ++kt) {
                const int kg = kc * 4 + kt;          // global k16 index 0..31
                const uint32_t ab = smb + A_SUB(kg >> 3);
                const uint32_t ainner = (uint32_t)((kg & 7) * 32);
                uint32_t ah[2][4], bh[2][4];
                #pragma unroll
                for (int mt = 0; mt < 2; ++mt)
                    ldsm4(ah[mt], ab + (aoffp[mt] ^ ainner));
                #pragma unroll
                for (int nt2 = 0; nt2 < 2; ++nt2)
                    ldsm4t(bh[nt2], bb + boffp[nt2] + ((uint32_t)kt << 12));
                #pragma unroll
                for (int mt = 0; mt < 2; ++mt)
                    #pragma unroll
                    for (int nt = 0; nt < 4; ++nt)
                        mma16816(c[mt][nt], ah[mt], &bh[nt >> 1][(nt & 1) * 2]);
            }
        }

        // ---- fused epilogue: bias + GELU + GEMM2 partial, registers only ----
        #pragma unroll
        for (int nt = 0; nt < 4; ++nt) {
            const int ncol = wn * 32 + nt * 8 + (lane & 3) * 2;
            const int ng = nc * NCHUNK + ncol;
            const float2 bv = *(const float2*)(b1s + ng);
            #pragma unroll
            for (int mt = 0; mt < 2; ++mt) {
                const float h0 = gelu_erf(c[mt][nt][0] + bv.x);
                const float h1 = gelu_erf(c[mt][nt][1] + bv.y);
                const float h2 = gelu_erf(c[mt][nt][2] + bv.x);
                const float h3 = gelu_erf(c[mt][nt][3] + bv.y);
                if (odim == 6) {
                    #pragma unroll
                    for (int o = 0; o < 6; ++o) {
                        const float2 w = *(const float2*)(w2t + o * W2STR + ng);
                        oacc[mt][0][o] += h0 * w.x + h1 * w.y;
                        oacc[mt][1][o] += h2 * w.x + h3 * w.y;
                    }
                } else {
                    #pragma unroll
                    for (int o = 0; o < 3; ++o) {
                        const float2 w = *(const float2*)(w2t + o * W2STR + ng);
                        oacc[mt][0][o] += h0 * w.x + h1 * w.y;
                        oacc[mt][1][o] += h2 * w.x + h3 * w.y;
                    }
                }
            }
        }
    }

    // ---- reduction: quad butterfly, then cross-warp via smem (aliased on B) ----
    #pragma unroll
    for (int mt = 0; mt < 2; ++mt)
        #pragma unroll
        for (int i = 0; i < 2; ++i)
            #pragma unroll
            for (int o = 0; o < 6; ++o) {
                float v = oacc[mt][i][o];
                v += __shfl_xor_sync(0xffffffffu, v, 1);
                v += __shfl_xor_sync(0xffffffffu, v, 2);
                oacc[mt][i][o] = v;
            }

    float* red = (float*)(sm + OFF_RED);
    __syncthreads();                       // all MMA done; no cp.async pending
    if ((lane & 3) == 0) {
        const int g = lane >> 2;
        #pragma unroll
        for (int mt = 0; mt < 2; ++mt)
            #pragma unroll
            for (int i = 0; i < 2; ++i) {
                const int row = wm * 32 + mt * 16 + i * 8 + g;
                #pragma unroll
                for (int o = 0; o < 6; ++o)
                    red[(wn * TM + row) * 8 + o] = oacc[mt][i][o];
            }
    }
    __syncthreads();

    #pragma unroll
    for (int p = 0; p < 2; ++p) {
        const int idx = tid + p * NTHREADS;
        if (idx < TM * odim) {
            const int m = idx / odim;
            const int o = idx - m * odim;
            const int token = tok0 + m;
            if (token < BT) {
                const float sdm = red[m * 8 + o] + red[(TM + m) * 8 + o]
                                + red[(2 * TM + m) * 8 + o] + red[(3 * TM + m) * 8 + o];
                out[(size_t)token * OUTC + colbase + o] = sdm + b2[o];
            }
        }
    }
}

extern "C" void kernel_launch(void* const* d_in, const int* in_sizes, int n_in,
                              void* d_out, int out_size)
{
    const float* x   = (const float*)d_in[0];
    const float* W1  = (const float*)d_in[1];
    const float* b1  = (const float*)d_in[2];
    const float* W2a = (const float*)d_in[3];
    const float* b2a = (const float*)d_in[4];
    const float* W2b = (const float*)d_in[5];
    const float* b2b = (const float*)d_in[6];
    float* out = (float*)d_out;

    // 1) preconvert W1 + x to fp16, single launch (exact grid)
    convert_all_kernel<<<(W1F4 + XF4) / 512, 512>>>(W1, x);

    // 2) fused fp16 GEMM: A resident, 2 CTAs/SM, incremental B addressing
    cudaFuncSetAttribute(motion_decoder_mma,
                         cudaFuncAttributeMaxDynamicSharedMemorySize, SMEM_BYTES);
    dim3 grid((BT + TM - 1) / TM, NJ);          // 49 x 43
    motion_decoder_mma<<<grid, NTHREADS, SMEM_BYTES>>>(b1, W2a, b2a, W2b, b2b, out);
}